// round 2
// baseline (speedup 1.0000x reference)
#include <cuda_runtime.h>

// ---------------------------------------------------------------------------
// NeuralODEModel: persistent per-thread dopri5 integrator.
// One thread = one batch row. h, k1..k5, y live in registers; weights live in
// SMEM (broadcast reads); per-thread constant part of layer-1 preactivation
// (b1 + se @ W1[16:32]) precomputed into SMEM once.
// ---------------------------------------------------------------------------

#define B_TOTAL 32768
#define T_STEPS 64
#define N_INJ   8
#define SID     7
#define SHD     16
#define OHD     16
#define MID     64
#define BLOCK   224
#define GRID    147   // 147*224 = 32928 >= 32768

// Shared memory layout (float offsets)
#define S_W1Y 0                       // [64][16]  W1 rows 0..15, transposed (j-major)
#define S_W2  1024                    // [64][16]  W2 (row-major copy)
#define S_C   2048                    // [64][BLOCK] per-thread const preactivation
#define S_W1D (2048 + 64*BLOCK)       // [64]      W1 row 32 (dose weights)
#define S_B2  (S_W1D + 64)            // [16]
#define S_WR  (S_B2 + 16)             // [16]
#define S_T   (S_WR + 16)             // [64]
#define S_BR  (S_T + 64)              // [1]
#define S_TOTAL (S_BR + 1)            // 16545 floats = 66180 bytes

__device__ __forceinline__ float tanh_fast(float x) {
    // (e^{2x}-1)/(e^{2x}+1); clamp avoids inf/inf. Abs err ~1e-7.
    float ax = fminf(fmaxf(x, -15.0f), 15.0f);
    float e  = __expf(2.0f * ax);
    return __fdividef(e - 1.0f, e + 1.0f);
}

__device__ __forceinline__ void f_eval(
    float tv,
    const float* __restrict__ y,      // [16] registers
    float* __restrict__ kout,         // [16] registers
    const float* __restrict__ sm,
    int tid,
    const float* __restrict__ itm,    // [8] injection times (regs)
    const float* __restrict__ idn)    // [8] injection doses (regs)
{
    // Gaussian dose bumps
    float dose = 0.0f;
    #pragma unroll
    for (int n = 0; n < N_INJ; n++) {
        float d = tv - itm[n];
        dose += idn[n] * __expf(-0.5f * d * d);
    }
    dose = fminf(fmaxf(dose, 0.0f), 100.0f);

    #pragma unroll
    for (int o = 0; o < OHD; o++) kout[o] = sm[S_B2 + o];

    const float* __restrict__ w1y = sm + S_W1Y;
    const float* __restrict__ w2  = sm + S_W2;
    const float* __restrict__ cg  = sm + S_C + tid;
    const float* __restrict__ w1d = sm + S_W1D;

    #pragma unroll 2
    for (int j = 0; j < MID; j++) {
        float z0 = cg[j * BLOCK] + dose * w1d[j];
        float4 wa = *(const float4*)(w1y + j * 16 + 0);
        float4 wb = *(const float4*)(w1y + j * 16 + 4);
        float4 wc = *(const float4*)(w1y + j * 16 + 8);
        float4 wd = *(const float4*)(w1y + j * 16 + 12);
        // two accumulator chains for ILP
        float zA = z0 + y[0] * wa.x + y[1] * wa.y + y[2] * wa.z + y[3] * wa.w
                      + y[4] * wb.x + y[5] * wb.y + y[6] * wb.z + y[7] * wb.w;
        float zB =      y[8] * wc.x + y[9] * wc.y + y[10] * wc.z + y[11] * wc.w
                      + y[12] * wd.x + y[13] * wd.y + y[14] * wd.z + y[15] * wd.w;
        float a = tanh_fast(zA + zB);

        float4 v0 = *(const float4*)(w2 + j * 16 + 0);
        float4 v1 = *(const float4*)(w2 + j * 16 + 4);
        float4 v2 = *(const float4*)(w2 + j * 16 + 8);
        float4 v3 = *(const float4*)(w2 + j * 16 + 12);
        kout[0]  += a * v0.x;  kout[1]  += a * v0.y;
        kout[2]  += a * v0.z;  kout[3]  += a * v0.w;
        kout[4]  += a * v1.x;  kout[5]  += a * v1.y;
        kout[6]  += a * v1.z;  kout[7]  += a * v1.w;
        kout[8]  += a * v2.x;  kout[9]  += a * v2.y;
        kout[10] += a * v2.z;  kout[11] += a * v2.w;
        kout[12] += a * v3.x;  kout[13] += a * v3.y;
        kout[14] += a * v3.z;  kout[15] += a * v3.w;
    }
}

extern "C" __global__ void __launch_bounds__(BLOCK, 1)
neural_ode_66236985639756(
    const float* __restrict__ t_g,
    const float* __restrict__ sf_g,
    const float* __restrict__ it_g,
    const float* __restrict__ id_g,
    const float* __restrict__ W_se, const float* __restrict__ b_se,
    const float* __restrict__ W_i,  const float* __restrict__ b_i,
    const float* __restrict__ W1,   const float* __restrict__ b1,
    const float* __restrict__ W2,   const float* __restrict__ b2,
    const float* __restrict__ Wr,   const float* __restrict__ br,
    float* __restrict__ out)
{
    extern __shared__ float sm[];
    const int tid = threadIdx.x;
    const int b   = blockIdx.x * BLOCK + tid;
    const bool valid = (b < B_TOTAL);

    // ---- cooperative SMEM init -------------------------------------------
    for (int idx = tid; idx < MID * 16; idx += BLOCK) {
        int j = idx >> 4, i = idx & 15;
        sm[S_W1Y + idx] = W1[i * MID + j];   // transpose rows 0..15
        sm[S_W2 + idx]  = W2[idx];
    }
    for (int idx = tid; idx < 64; idx += BLOCK) {
        sm[S_W1D + idx] = W1[32 * MID + idx];
        sm[S_T + idx]   = t_g[idx];
    }
    if (tid < 16) { sm[S_B2 + tid] = b2[tid]; sm[S_WR + tid] = Wr[tid]; }
    if (tid == 0) { sm[S_BR] = br[0]; }

    // ---- per-thread static embed + h0 ------------------------------------
    float se[SHD];
    {
        float sfv[SID];
        #pragma unroll
        for (int i = 0; i < SID; i++) sfv[i] = valid ? sf_g[b * SID + i] : 0.0f;
        #pragma unroll
        for (int o = 0; o < SHD; o++) {
            float acc = b_se[o];
            #pragma unroll
            for (int i = 0; i < SID; i++) acc += sfv[i] * W_se[i * SHD + o];
            se[o] = fmaxf(acc, 0.0f);
        }
    }
    float h[OHD];
    #pragma unroll
    for (int o = 0; o < OHD; o++) {
        float acc = b_i[o];
        #pragma unroll
        for (int i = 0; i < SHD; i++) acc += se[i] * W_i[i * OHD + o];
        h[o] = acc;
    }
    // per-thread constant layer-1 preactivation: b1 + se @ W1[16:32]
    for (int j = 0; j < MID; j++) {
        float acc = b1[j];
        #pragma unroll
        for (int i = 0; i < SHD; i++) acc += se[i] * W1[(16 + i) * MID + j];
        sm[S_C + j * BLOCK + tid] = acc;
    }
    float itm[N_INJ], idn[N_INJ];
    #pragma unroll
    for (int n = 0; n < N_INJ; n++) {
        itm[n] = valid ? it_g[b * N_INJ + n] : 1.0e9f;
        idn[n] = valid ? id_g[b * N_INJ + n] : 0.0f;
    }
    __syncthreads();

    // ---- t=0 readout ------------------------------------------------------
    if (valid) {
        float o = sm[S_BR];
        #pragma unroll
        for (int i = 0; i < OHD; i++) o += h[i] * sm[S_WR + i];
        out[b * T_STEPS] = fmaxf(o, 0.0f);
    }

    // ---- dopri5 coefficients ---------------------------------------------
    const float A21 = 0.2f;
    const float A31 = 0.075f, A32 = 0.225f;
    const float A41 = (float)(44.0/45.0),      A42 = (float)(-56.0/15.0),
                A43 = (float)(32.0/9.0);
    const float A51 = (float)(19372.0/6561.0), A52 = (float)(-25360.0/2187.0),
                A53 = (float)(64448.0/6561.0), A54 = (float)(-212.0/729.0);
    const float A61 = (float)(9017.0/3168.0),  A62 = (float)(-355.0/33.0),
                A63 = (float)(46732.0/5247.0), A64 = (float)(49.0/176.0),
                A65 = (float)(-5103.0/18656.0);
    const float B1 = (float)(35.0/384.0),   B3 = (float)(500.0/1113.0),
                B4 = (float)(125.0/192.0),  B5 = (float)(-2187.0/6784.0),
                B6 = (float)(11.0/84.0);
    const float C2 = 0.2f, C3 = 0.3f, C4 = 0.8f, C5 = (float)(8.0/9.0);

    float k1[OHD], k2[OHD], k3[OHD], k4[OHD], k5[OHD], y[OHD];

    #pragma unroll 1
    for (int step = 0; step < T_STEPS - 1; ++step) {
        float t0 = sm[S_T + step], t1 = sm[S_T + step + 1];
        float dt = (t1 - t0) * 0.5f;
        #pragma unroll 1
        for (int sub = 0; sub < 2; ++sub) {
            float tv = t0 + sub * dt;

            f_eval(tv, h, k1, sm, tid, itm, idn);

            #pragma unroll
            for (int i = 0; i < OHD; i++) y[i] = fmaf(dt * A21, k1[i], h[i]);
            f_eval(tv + C2 * dt, y, k2, sm, tid, itm, idn);

            #pragma unroll
            for (int i = 0; i < OHD; i++)
                y[i] = h[i] + dt * (A31 * k1[i] + A32 * k2[i]);
            f_eval(tv + C3 * dt, y, k3, sm, tid, itm, idn);

            #pragma unroll
            for (int i = 0; i < OHD; i++)
                y[i] = h[i] + dt * (A41 * k1[i] + A42 * k2[i] + A43 * k3[i]);
            f_eval(tv + C4 * dt, y, k4, sm, tid, itm, idn);

            #pragma unroll
            for (int i = 0; i < OHD; i++)
                y[i] = h[i] + dt * (A51 * k1[i] + A52 * k2[i] + A53 * k3[i]
                                    + A54 * k4[i]);
            f_eval(tv + C5 * dt, y, k5, sm, tid, itm, idn);

            #pragma unroll
            for (int i = 0; i < OHD; i++)
                y[i] = h[i] + dt * (A61 * k1[i] + A62 * k2[i] + A63 * k3[i]
                                    + A64 * k4[i] + A65 * k5[i]);
            // k2 is dead now; reuse its registers for k6
            f_eval(tv + dt, y, k2, sm, tid, itm, idn);

            #pragma unroll
            for (int i = 0; i < OHD; i++)
                h[i] += dt * (B1 * k1[i] + B3 * k3[i] + B4 * k4[i]
                              + B5 * k5[i] + B6 * k2[i]);
        }
        if (valid) {
            float o = sm[S_BR];
            #pragma unroll
            for (int i = 0; i < OHD; i++) o += h[i] * sm[S_WR + i];
            out[b * T_STEPS + step + 1] = fmaxf(o, 0.0f);
        }
    }
}

extern "C" void kernel_launch(void* const* d_in, const int* in_sizes, int n_in,
                              void* d_out, int out_size)
{
    (void)in_sizes; (void)n_in; (void)out_size;
    cudaFuncSetAttribute(neural_ode_66236985639756,
                         cudaFuncAttributeMaxDynamicSharedMemorySize,
                         S_TOTAL * sizeof(float));
    neural_ode_66236985639756<<<GRID, BLOCK, S_TOTAL * sizeof(float)>>>(
        (const float*)d_in[0],  // t
        (const float*)d_in[1],  // static_features
        (const float*)d_in[2],  // injection_times
        (const float*)d_in[3],  // injection_doses
        (const float*)d_in[4],  // W_se
        (const float*)d_in[5],  // b_se
        (const float*)d_in[6],  // W_i
        (const float*)d_in[7],  // b_i
        (const float*)d_in[8],  // W1
        (const float*)d_in[9],  // b1
        (const float*)d_in[10], // W2
        (const float*)d_in[11], // b2
        (const float*)d_in[12], // Wr
        (const float*)d_in[13], // br
        (float*)d_out);
}

// round 3
// speedup vs baseline: 1.4145x; 1.4145x over previous
#include <cuda_runtime.h>

// ---------------------------------------------------------------------------
// NeuralODEModel: persistent per-thread dopri5 integrator, f32x2-packed.
// One thread = one batch row. All RK state lives in packed f32x2 registers;
// weights in SMEM; per-thread const part of layer-1 preactivation in SMEM.
// ---------------------------------------------------------------------------

#define B_TOTAL 32768
#define T_STEPS 64
#define N_INJ   8
#define SID     7
#define SHD     16
#define OHD     16
#define MID     64
#define BLOCK   224
#define GRID    147   // 147*224 = 32928 >= 32768

// Shared memory layout (float offsets)
#define S_W1Y 0                       // [64][16]  W1 rows 0..15, transposed (j-major)
#define S_W2  1024                    // [64][16]  W2 (row-major copy)
#define S_C   2048                    // [64][BLOCK] per-thread const preactivation
#define S_W1D (2048 + 64*BLOCK)       // [64]      W1 row 32 (dose weights)
#define S_B2  (S_W1D + 64)            // [16]
#define S_WR  (S_B2 + 16)             // [16]
#define S_T   (S_WR + 16)             // [64]
#define S_BR  (S_T + 64)              // [1]
#define S_TOTAL (S_BR + 1)

typedef unsigned long long u64;

// ---- packed f32x2 primitives (Blackwell-only; ptxas won't auto-fuse) ------
__device__ __forceinline__ u64 pk2(float lo, float hi) {
    u64 r; asm("mov.b64 %0,{%1,%2};" : "=l"(r) : "f"(lo), "f"(hi)); return r;
}
__device__ __forceinline__ u64 pks(float x) { return pk2(x, x); }
__device__ __forceinline__ void upk(u64 v, float& lo, float& hi) {
    asm("mov.b64 {%0,%1},%2;" : "=f"(lo), "=f"(hi) : "l"(v));
}
__device__ __forceinline__ u64 f2fma(u64 a, u64 b, u64 c) {
    u64 d; asm("fma.rn.f32x2 %0,%1,%2,%3;" : "=l"(d) : "l"(a), "l"(b), "l"(c)); return d;
}
__device__ __forceinline__ u64 f2mul(u64 a, u64 b) {
    u64 d; asm("mul.rn.f32x2 %0,%1,%2;" : "=l"(d) : "l"(a), "l"(b)); return d;
}
__device__ __forceinline__ u64 f2add(u64 a, u64 b) {
    u64 d; asm("add.rn.f32x2 %0,%1,%2;" : "=l"(d) : "l"(a), "l"(b)); return d;
}
__device__ __forceinline__ float tanhap(float x) {
    float r; asm("tanh.approx.f32 %0,%1;" : "=f"(r) : "f"(x)); return r;
}

// ---- ODE right-hand side: one MLP eval, packed --------------------------
__device__ __forceinline__ void f_eval(
    float tv,
    const u64* __restrict__ y,        // [8] packed (16 floats)
    u64* __restrict__ kout,           // [8] packed
    const float* __restrict__ sm,
    int tid,
    const float* __restrict__ itm,    // [8] regs
    const float* __restrict__ idn)    // [8] regs
{
    float dose = 0.0f;
    #pragma unroll
    for (int n = 0; n < N_INJ; n++) {
        float d = tv - itm[n];
        dose += idn[n] * __expf(-0.5f * d * d);
    }
    dose = fminf(fmaxf(dose, 0.0f), 100.0f);

    const ulonglong2* __restrict__ w1y = (const ulonglong2*)(sm + S_W1Y);
    const ulonglong2* __restrict__ w2  = (const ulonglong2*)(sm + S_W2);
    const float* __restrict__ cg  = sm + S_C + tid;
    const float* __restrict__ w1d = sm + S_W1D;
    const ulonglong2* __restrict__ b2p = (const ulonglong2*)(sm + S_B2);

    {
        ulonglong2 q0 = b2p[0], q1 = b2p[1], q2 = b2p[2], q3 = b2p[3];
        kout[0] = q0.x; kout[1] = q0.y; kout[2] = q1.x; kout[3] = q1.y;
        kout[4] = q2.x; kout[5] = q2.y; kout[6] = q3.x; kout[7] = q3.y;
    }

    #pragma unroll 4
    for (int j = 0; j < MID; j++) {
        float z0 = fmaf(dose, w1d[j], cg[j * BLOCK]);
        ulonglong2 a0 = w1y[j * 4 + 0], a1 = w1y[j * 4 + 1];
        ulonglong2 a2 = w1y[j * 4 + 2], a3 = w1y[j * 4 + 3];
        // two packed accumulator chains (16 MACs in 8 FFMA2)
        u64 s0 = f2fma(y[0], a0.x, pk2(z0, 0.0f));
        u64 s1 = f2mul(y[1], a0.y);
        s0 = f2fma(y[2], a1.x, s0);
        s1 = f2fma(y[3], a1.y, s1);
        s0 = f2fma(y[4], a2.x, s0);
        s1 = f2fma(y[5], a2.y, s1);
        s0 = f2fma(y[6], a3.x, s0);
        s1 = f2fma(y[7], a3.y, s1);
        u64 s = f2add(s0, s1);
        float slo, shi; upk(s, slo, shi);
        float a = tanhap(slo + shi);
        u64 aa = pks(a);

        ulonglong2 v0 = w2[j * 4 + 0], v1 = w2[j * 4 + 1];
        ulonglong2 v2 = w2[j * 4 + 2], v3 = w2[j * 4 + 3];
        kout[0] = f2fma(aa, v0.x, kout[0]);
        kout[1] = f2fma(aa, v0.y, kout[1]);
        kout[2] = f2fma(aa, v1.x, kout[2]);
        kout[3] = f2fma(aa, v1.y, kout[3]);
        kout[4] = f2fma(aa, v2.x, kout[4]);
        kout[5] = f2fma(aa, v2.y, kout[5]);
        kout[6] = f2fma(aa, v3.x, kout[6]);
        kout[7] = f2fma(aa, v3.y, kout[7]);
    }
}

extern "C" __global__ void __launch_bounds__(BLOCK, 1)
neural_ode_66236985639756(
    const float* __restrict__ t_g,
    const float* __restrict__ sf_g,
    const float* __restrict__ it_g,
    const float* __restrict__ id_g,
    const float* __restrict__ W_se, const float* __restrict__ b_se,
    const float* __restrict__ W_i,  const float* __restrict__ b_i,
    const float* __restrict__ W1,   const float* __restrict__ b1,
    const float* __restrict__ W2,   const float* __restrict__ b2,
    const float* __restrict__ Wr,   const float* __restrict__ br,
    float* __restrict__ out)
{
    extern __shared__ float sm[];
    const int tid = threadIdx.x;
    const int b   = blockIdx.x * BLOCK + tid;
    const bool valid = (b < B_TOTAL);

    // ---- cooperative SMEM init -------------------------------------------
    for (int idx = tid; idx < MID * 16; idx += BLOCK) {
        int j = idx >> 4, i = idx & 15;
        sm[S_W1Y + idx] = W1[i * MID + j];   // transpose rows 0..15
        sm[S_W2 + idx]  = W2[idx];
    }
    for (int idx = tid; idx < 64; idx += BLOCK) {
        sm[S_W1D + idx] = W1[32 * MID + idx];
        sm[S_T + idx]   = t_g[idx];
    }
    if (tid < 16) { sm[S_B2 + tid] = b2[tid]; sm[S_WR + tid] = Wr[tid]; }
    if (tid == 0) { sm[S_BR] = br[0]; }

    // ---- per-thread static embed + h0 ------------------------------------
    float se[SHD];
    {
        float sfv[SID];
        #pragma unroll
        for (int i = 0; i < SID; i++) sfv[i] = valid ? sf_g[b * SID + i] : 0.0f;
        #pragma unroll
        for (int o = 0; o < SHD; o++) {
            float acc = b_se[o];
            #pragma unroll
            for (int i = 0; i < SID; i++) acc += sfv[i] * W_se[i * SHD + o];
            se[o] = fmaxf(acc, 0.0f);
        }
    }
    float h_s[OHD];
    #pragma unroll
    for (int o = 0; o < OHD; o++) {
        float acc = b_i[o];
        #pragma unroll
        for (int i = 0; i < SHD; i++) acc += se[i] * W_i[i * OHD + o];
        h_s[o] = acc;
    }
    // per-thread constant layer-1 preactivation: b1 + se @ W1[16:32]
    for (int j = 0; j < MID; j++) {
        float acc = b1[j];
        #pragma unroll
        for (int i = 0; i < SHD; i++) acc += se[i] * W1[(16 + i) * MID + j];
        sm[S_C + j * BLOCK + tid] = acc;
    }
    float itm[N_INJ], idn[N_INJ];
    #pragma unroll
    for (int n = 0; n < N_INJ; n++) {
        itm[n] = valid ? it_g[b * N_INJ + n] : 1.0e9f;
        idn[n] = valid ? id_g[b * N_INJ + n] : 0.0f;
    }
    __syncthreads();

    // packed state
    u64 h[8];
    #pragma unroll
    for (int p = 0; p < 8; p++) h[p] = pk2(h_s[2 * p], h_s[2 * p + 1]);

    // ---- t=0 readout ------------------------------------------------------
    const ulonglong2* __restrict__ wrp = (const ulonglong2*)(sm + S_WR);
    if (valid) {
        ulonglong2 wr0 = wrp[0], wr1 = wrp[1], wr2 = wrp[2], wr3 = wrp[3];
        u64 acc = f2mul(h[0], wr0.x);
        acc = f2fma(h[1], wr0.y, acc);
        acc = f2fma(h[2], wr1.x, acc);
        acc = f2fma(h[3], wr1.y, acc);
        acc = f2fma(h[4], wr2.x, acc);
        acc = f2fma(h[5], wr2.y, acc);
        acc = f2fma(h[6], wr3.x, acc);
        acc = f2fma(h[7], wr3.y, acc);
        float lo, hi; upk(acc, lo, hi);
        out[b * T_STEPS] = fmaxf(sm[S_BR] + lo + hi, 0.0f);
    }

    // ---- dopri5 coefficients ---------------------------------------------
    const float A21 = 0.2f;
    const float A31 = 0.075f, A32 = 0.225f;
    const float A41 = (float)(44.0/45.0),      A42 = (float)(-56.0/15.0),
                A43 = (float)(32.0/9.0);
    const float A51 = (float)(19372.0/6561.0), A52 = (float)(-25360.0/2187.0),
                A53 = (float)(64448.0/6561.0), A54 = (float)(-212.0/729.0);
    const float A61 = (float)(9017.0/3168.0),  A62 = (float)(-355.0/33.0),
                A63 = (float)(46732.0/5247.0), A64 = (float)(49.0/176.0),
                A65 = (float)(-5103.0/18656.0);
    const float B1c = (float)(35.0/384.0),  B3c = (float)(500.0/1113.0),
                B4c = (float)(125.0/192.0), B5c = (float)(-2187.0/6784.0),
                B6c = (float)(11.0/84.0);
    const float C2 = 0.2f, C3 = 0.3f, C4 = 0.8f, C5 = (float)(8.0/9.0);

    u64 k1[8], k2[8], k3[8], k4[8], k5[8], y[8];

    #pragma unroll 1
    for (int step = 0; step < T_STEPS - 1; ++step) {
        float t0 = sm[S_T + step], t1 = sm[S_T + step + 1];
        float dt = (t1 - t0) * 0.5f;
        #pragma unroll 1
        for (int sub = 0; sub < 2; ++sub) {
            float tv = t0 + sub * dt;

            f_eval(tv, h, k1, sm, tid, itm, idn);

            {
                u64 c21 = pks(dt * A21);
                #pragma unroll
                for (int p = 0; p < 8; p++) y[p] = f2fma(c21, k1[p], h[p]);
            }
            f_eval(tv + C2 * dt, y, k2, sm, tid, itm, idn);

            {
                u64 c1 = pks(dt * A31), c2 = pks(dt * A32);
                #pragma unroll
                for (int p = 0; p < 8; p++)
                    y[p] = f2fma(c1, k1[p], f2fma(c2, k2[p], h[p]));
            }
            f_eval(tv + C3 * dt, y, k3, sm, tid, itm, idn);

            {
                u64 c1 = pks(dt * A41), c2 = pks(dt * A42), c3 = pks(dt * A43);
                #pragma unroll
                for (int p = 0; p < 8; p++) {
                    u64 acc = f2fma(c3, k3[p], h[p]);
                    acc = f2fma(c2, k2[p], acc);
                    y[p] = f2fma(c1, k1[p], acc);
                }
            }
            f_eval(tv + C4 * dt, y, k4, sm, tid, itm, idn);

            {
                u64 c1 = pks(dt * A51), c2 = pks(dt * A52),
                    c3 = pks(dt * A53), c4 = pks(dt * A54);
                #pragma unroll
                for (int p = 0; p < 8; p++) {
                    u64 acc = f2fma(c4, k4[p], h[p]);
                    acc = f2fma(c3, k3[p], acc);
                    acc = f2fma(c2, k2[p], acc);
                    y[p] = f2fma(c1, k1[p], acc);
                }
            }
            f_eval(tv + C5 * dt, y, k5, sm, tid, itm, idn);

            {
                u64 c1 = pks(dt * A61), c2 = pks(dt * A62), c3 = pks(dt * A63),
                    c4 = pks(dt * A64), c5 = pks(dt * A65);
                #pragma unroll
                for (int p = 0; p < 8; p++) {
                    u64 acc = f2fma(c5, k5[p], h[p]);
                    acc = f2fma(c4, k4[p], acc);
                    acc = f2fma(c3, k3[p], acc);
                    acc = f2fma(c2, k2[p], acc);
                    y[p] = f2fma(c1, k1[p], acc);
                }
            }
            // k2 is dead; reuse as k6
            f_eval(tv + dt, y, k2, sm, tid, itm, idn);

            {
                u64 c1 = pks(dt * B1c), c3 = pks(dt * B3c), c4 = pks(dt * B4c),
                    c5 = pks(dt * B5c), c6 = pks(dt * B6c);
                #pragma unroll
                for (int p = 0; p < 8; p++) {
                    u64 acc = f2fma(c6, k2[p], h[p]);
                    acc = f2fma(c5, k5[p], acc);
                    acc = f2fma(c4, k4[p], acc);
                    acc = f2fma(c3, k3[p], acc);
                    h[p] = f2fma(c1, k1[p], acc);
                }
            }
        }
        if (valid) {
            ulonglong2 wr0 = wrp[0], wr1 = wrp[1], wr2 = wrp[2], wr3 = wrp[3];
            u64 acc = f2mul(h[0], wr0.x);
            acc = f2fma(h[1], wr0.y, acc);
            acc = f2fma(h[2], wr1.x, acc);
            acc = f2fma(h[3], wr1.y, acc);
            acc = f2fma(h[4], wr2.x, acc);
            acc = f2fma(h[5], wr2.y, acc);
            acc = f2fma(h[6], wr3.x, acc);
            acc = f2fma(h[7], wr3.y, acc);
            float lo, hi; upk(acc, lo, hi);
            out[b * T_STEPS + step + 1] = fmaxf(sm[S_BR] + lo + hi, 0.0f);
        }
    }
}

extern "C" void kernel_launch(void* const* d_in, const int* in_sizes, int n_in,
                              void* d_out, int out_size)
{
    (void)in_sizes; (void)n_in; (void)out_size;
    cudaFuncSetAttribute(neural_ode_66236985639756,
                         cudaFuncAttributeMaxDynamicSharedMemorySize,
                         S_TOTAL * sizeof(float));
    neural_ode_66236985639756<<<GRID, BLOCK, S_TOTAL * sizeof(float)>>>(
        (const float*)d_in[0],  // t
        (const float*)d_in[1],  // static_features
        (const float*)d_in[2],  // injection_times
        (const float*)d_in[3],  // injection_doses
        (const float*)d_in[4],  // W_se
        (const float*)d_in[5],  // b_se
        (const float*)d_in[6],  // W_i
        (const float*)d_in[7],  // b_i
        (const float*)d_in[8],  // W1
        (const float*)d_in[9],  // b1
        (const float*)d_in[10], // W2
        (const float*)d_in[11], // b2
        (const float*)d_in[12], // Wr
        (const float*)d_in[13], // br
        (float*)d_out);
}